// round 13
// baseline (speedup 1.0000x reference)
#include <cuda_runtime.h>
#include <cstddef>

// ---------------------------------------------------------------------------
// learn_wavelet: 3-level learnable lifting wavelet.
// Subnets: packed f32x2 FMA; hidden in SMEM as fp32 channel-pairs, 4 pairs per
// position (32B), 2 passes of 8 channels. Tile 32x32 with 4 blocks/SM
// (49.5KB SMEM, reg cap 64) to double resident warps at near-R9 bytes/px.
// Stage-1: 2 adjacent hidden positions/thread. Stage-2: 2x2 px/thread.
// Swizzle for THIS layout: swz64(b) = b ^ ((b>>2)&0x70) (bits[6:8]->[4:6]);
// stage-2 lane stride is 64B so the old >>3 swizzle would 2-way conflict.
// Identity swz64(x+16) == swz64(x)^16 for x % 32 == 0.
// ---------------------------------------------------------------------------

#define NIMG 24
typedef unsigned long long ull;

// Scratch (device globals: allocation-free per harness rules)
__device__ float g_L [NIMG * 256 * 512];
__device__ float g_H [NIMG * 256 * 512];
__device__ float g_LL[NIMG * 256 * 256];
__device__ float g_HL[NIMG * 256 * 256];
__device__ float g_LH[NIMG * 256 * 256];
__device__ float g_HH[NIMG * 256 * 256];

// Channel-paired weights: pair p holds (ch 2p, ch 2p+1) in (lo, hi).
struct PackedW {
    ull   w1[2][8][9];   // [pset][pair][tap]
    ull   b1[2][8];
    ull   w2[2][8][9];
    float b2[2];
    float pad[2];
};
__device__   PackedW g_pack;
__constant__ PackedW c_pack;

// ---------------- packed f32x2 helpers ----------------
__device__ __forceinline__ ull fma2(ull a, ull b, ull c) {
    ull d; asm("fma.rn.f32x2 %0, %1, %2, %3;" : "=l"(d) : "l"(a), "l"(b), "l"(c));
    return d;
}
__device__ __forceinline__ ull pack2(float lo, float hi) {
    ull d;
    asm("mov.b64 %0, {%1, %2};" : "=l"(d)
        : "r"(__float_as_uint(lo)), "r"(__float_as_uint(hi)));
    return d;
}
__device__ __forceinline__ float2 unpack2(ull a) {
    unsigned lo, hi;
    asm("mov.b64 {%0, %1}, %2;" : "=r"(lo), "=r"(hi) : "l"(a));
    return make_float2(__uint_as_float(lo), __uint_as_float(hi));
}

// XOR swizzle for 64B-strided phases: bits[6:8] -> bits[4:6].
__device__ __forceinline__ unsigned swz64(unsigned b) {
    return b ^ ((b >> 2) & 0x70);
}

// SMEM partition (dynamic): sH (34*36*32 = 39168B) then sIn (36*36*8 = 10368B)
#define SH_BYTES   (34 * 36 * 32)
#define SMEM_TOTAL (SH_BYTES + 36 * 36 * 8)

// ---------------------------------------------------------------------------
// Prep kernel: pack channel-paired weights into g_pack (then memcpy to const).
// ---------------------------------------------------------------------------
__global__ void prep_kernel(const float* __restrict__ Wp1, const float* __restrict__ bp1,
                            const float* __restrict__ Wp2, const float* __restrict__ bp2,
                            const float* __restrict__ Wu1, const float* __restrict__ bu1,
                            const float* __restrict__ Wu2, const float* __restrict__ bu2)
{
    int t = threadIdx.x;
    const float* W1s[2] = {Wp1, Wu1};
    const float* B1s[2] = {bp1, bu1};
    const float* W2s[2] = {Wp2, Wu2};
    const float* B2s[2] = {bp2, bu2};
    if (t < 144) {
        int ps = t / 72, r = t - ps * 72, p = r / 9, k = r - p * 9;
        *(float2*)&g_pack.w1[ps][p][k] =
            make_float2(W1s[ps][(2 * p) * 9 + k], W1s[ps][(2 * p + 1) * 9 + k]);
        *(float2*)&g_pack.w2[ps][p][k] =
            make_float2(W2s[ps][(2 * p) * 9 + k], W2s[ps][(2 * p + 1) * 9 + k]);
    }
    if (t < 16) {
        int ps = t / 8, p = t - ps * 8;
        *(float2*)&g_pack.b1[ps][p] = make_float2(B1s[ps][2 * p], B1s[ps][2 * p + 1]);
    }
    if (t < 2) g_pack.b2[t] = B2s[t][0];
}

// ---------------------------------------------------------------------------
// Kernel 1: RGB->YUV + even/odd row split.
// ---------------------------------------------------------------------------
__global__ void yuv_split_kernel(const float* __restrict__ x,
                                 float* __restrict__ L, float* __restrict__ H)
{
    int b   = blockIdx.y;
    int idx = blockIdx.x * 256 + threadIdx.x;
    int y   = idx >> 9;
    int xx  = idx & 511;

    const float* xb = x + (size_t)b * 3 * 262144;
    float r  = xb[idx];
    float g  = xb[262144 + idx];
    float bl = xb[2 * 262144 + idx];

    float Y =  0.299f * r + 0.587f * g + 0.114f * bl;
    float U = -0.147f * r - 0.289f * g + 0.436f * bl;
    float V =  0.615f * r - 0.515f * g - 0.100f * bl;

    float* dst = (y & 1) ? H : L;
    size_t o = (size_t)(y >> 1) * 512 + xx;
    const size_t istr = (size_t)256 * 512;
    dst[(size_t)(0 * 8 + b) * istr + o] = Y;
    dst[(size_t)(1 * 8 + b) * istr + o] = U;
    dst[(size_t)(2 * 8 + b) * istr + o] = V;
}

// ---------------------------------------------------------------------------
// Stage-1 helper: conv 1->8 (pairs 4g..4g+3) + relu for TWO adjacent hidden
// positions per thread. Taps via LDS.128 of duplicated float2 input.
// Hidden grid 34 rows x 34 cols. CHK=false for interior blocks.
// ---------------------------------------------------------------------------
template <bool CHK>
__device__ __forceinline__ void stage1(const float2* sIn, char* sHb,
                                       int pset, int g, int by, int bx,
                                       int h, int w, int tid)
{
    // 34 rows x 17 column pairs (hx = 0,2,...,32)
    for (int idx = tid; idx < 34 * 17; idx += 256) {
        int hy = idx / 17, hp = idx - hy * 17;
        int hx = hp * 2;

        ull cA0 = c_pack.b1[pset][4 * g + 0];
        ull cA1 = c_pack.b1[pset][4 * g + 1];
        ull cA2 = c_pack.b1[pset][4 * g + 2];
        ull cA3 = c_pack.b1[pset][4 * g + 3];
        ull cB0 = cA0, cB1 = cA1, cB2 = cA2, cB3 = cA3;   // pos hx+1

#pragma unroll
        for (int dy = 0; dy < 3; dy++) {
            const ull* row = (const ull*)&sIn[(hy + dy) * 36 + hx];
            ulonglong2 ta = *(const ulonglong2*)row;        // taps hx, hx+1
            ulonglong2 tb = *(const ulonglong2*)(row + 2);  // taps hx+2, hx+3
            ull t0 = ta.x, t1 = ta.y, t2 = tb.x, t3 = tb.y;

            ull w0 = c_pack.w1[pset][4 * g + 0][dy * 3 + 0];
            ull w1 = c_pack.w1[pset][4 * g + 0][dy * 3 + 1];
            ull w2 = c_pack.w1[pset][4 * g + 0][dy * 3 + 2];
            cA0 = fma2(w0, t0, cA0); cB0 = fma2(w0, t1, cB0);
            cA0 = fma2(w1, t1, cA0); cB0 = fma2(w1, t2, cB0);
            cA0 = fma2(w2, t2, cA0); cB0 = fma2(w2, t3, cB0);

            w0 = c_pack.w1[pset][4 * g + 1][dy * 3 + 0];
            w1 = c_pack.w1[pset][4 * g + 1][dy * 3 + 1];
            w2 = c_pack.w1[pset][4 * g + 1][dy * 3 + 2];
            cA1 = fma2(w0, t0, cA1); cB1 = fma2(w0, t1, cB1);
            cA1 = fma2(w1, t1, cA1); cB1 = fma2(w1, t2, cB1);
            cA1 = fma2(w2, t2, cA1); cB1 = fma2(w2, t3, cB1);

            w0 = c_pack.w1[pset][4 * g + 2][dy * 3 + 0];
            w1 = c_pack.w1[pset][4 * g + 2][dy * 3 + 1];
            w2 = c_pack.w1[pset][4 * g + 2][dy * 3 + 2];
            cA2 = fma2(w0, t0, cA2); cB2 = fma2(w0, t1, cB2);
            cA2 = fma2(w1, t1, cA2); cB2 = fma2(w1, t2, cB2);
            cA2 = fma2(w2, t2, cA2); cB2 = fma2(w2, t3, cB2);

            w0 = c_pack.w1[pset][4 * g + 3][dy * 3 + 0];
            w1 = c_pack.w1[pset][4 * g + 3][dy * 3 + 1];
            w2 = c_pack.w1[pset][4 * g + 3][dy * 3 + 2];
            cA3 = fma2(w0, t0, cA3); cB3 = fma2(w0, t1, cB3);
            cA3 = fma2(w1, t1, cA3); cB3 = fma2(w1, t2, cB3);
            cA3 = fma2(w2, t2, cA3); cB3 = fma2(w2, t3, cB3);
        }

        bool validA = true, validB = true;
        if (CHK) {
            int gy = by + hy - 1, gx = bx + hx - 1;
            bool vy = (gy >= 0 && gy < h);
            validA = vy && (gx >= 0 && gx < w);
            validB = vy && (gx + 1 >= 0 && gx + 1 < w);
        }

        unsigned b00 = (unsigned)(hy * 36 + hx) * 32;
        {   // pos hx
            float2 f0 = unpack2(cA0), f1 = unpack2(cA1),
                   f2 = unpack2(cA2), f3 = unpack2(cA3);
            float4 v0 = make_float4(validA ? fmaxf(f0.x, 0.f) : 0.f,
                                    validA ? fmaxf(f0.y, 0.f) : 0.f,
                                    validA ? fmaxf(f1.x, 0.f) : 0.f,
                                    validA ? fmaxf(f1.y, 0.f) : 0.f);
            float4 v1 = make_float4(validA ? fmaxf(f2.x, 0.f) : 0.f,
                                    validA ? fmaxf(f2.y, 0.f) : 0.f,
                                    validA ? fmaxf(f3.x, 0.f) : 0.f,
                                    validA ? fmaxf(f3.y, 0.f) : 0.f);
            unsigned a0 = swz64(b00);
            *(float4*)(sHb + a0)        = v0;   // pairs 4g, 4g+1
            *(float4*)(sHb + (a0 ^ 16)) = v1;   // pairs 4g+2, 4g+3
        }
        {   // pos hx+1
            float2 f0 = unpack2(cB0), f1 = unpack2(cB1),
                   f2 = unpack2(cB2), f3 = unpack2(cB3);
            float4 v0 = make_float4(validB ? fmaxf(f0.x, 0.f) : 0.f,
                                    validB ? fmaxf(f0.y, 0.f) : 0.f,
                                    validB ? fmaxf(f1.x, 0.f) : 0.f,
                                    validB ? fmaxf(f1.y, 0.f) : 0.f);
            float4 v1 = make_float4(validB ? fmaxf(f2.x, 0.f) : 0.f,
                                    validB ? fmaxf(f2.y, 0.f) : 0.f,
                                    validB ? fmaxf(f3.x, 0.f) : 0.f,
                                    validB ? fmaxf(f3.y, 0.f) : 0.f);
            unsigned a1 = swz64(b00 + 32);
            *(float4*)(sHb + a1)        = v0;
            *(float4*)(sHb + (a1 ^ 16)) = v1;
        }
    }
}

// ---------------------------------------------------------------------------
// Kernel 2: fused subnet + lift.  O[p] = S[p] + sign*subnet(I)[p]
// Tile 32w x 32h, 256 threads, 2 passes of 8 channels (4 pairs, 32B/pos).
// Stage-2: 2x2 px/thread (rows 2r,2r+1 x cols oxq,oxq+1).
// grid.z in [0, 2*NIMG): z < NIMG uses buffer set A, else set B.
// __launch_bounds__(256,4): 4 blocks/SM (49.5KB SMEM each, reg cap 64).
// SAME padding of conv2 zero-pads the *hidden* tensor (off-image hidden = 0).
// ---------------------------------------------------------------------------
__global__ void __launch_bounds__(256, 4)
subnet_lift_kernel(const float* __restrict__ IA, const float* __restrict__ SA,
                   float* __restrict__ OA,
                   const float* __restrict__ IB, const float* __restrict__ SB,
                   float* __restrict__ OB,
                   int pset, float sign, int h, int w)
{
    extern __shared__ char dynsmem[];
    char*   sHb = dynsmem;                          // 34*36 pos * 32B
    float2* sIn = (float2*)(dynsmem + SH_BYTES);    // 36 rows * 36 cols, dup'd

    const int tid = threadIdx.x;
    int z = blockIdx.z;
    const int setB = (z >= NIMG);
    const int img  = setB ? z - NIMG : z;
    const float* I = setB ? IB : IA;
    const float* S = setB ? SB : SA;
    float*       O = setB ? OB : OA;

    const int bx = blockIdx.x * 32;
    const int by = blockIdx.y * 32;
    const float* Ii = I + (size_t)img * h * w;

    const bool interior = (bx >= 2) && (bx + 34 <= w) &&
                          (by >= 2) && (by + 34 <= h);

    // --- load input tile (rows by-2..by+33, cols bx-2..bx+33), duplicated ---
    if (interior) {
        for (int idx = tid; idx < 36 * 36; idx += 256) {
            int ly = idx / 36, lx = idx - ly * 36;
            float v = Ii[(size_t)(by + ly - 2) * w + (bx + lx - 2)];
            sIn[idx] = make_float2(v, v);
        }
    } else {
        for (int idx = tid; idx < 36 * 36; idx += 256) {
            int ly = idx / 36, lx = idx - ly * 36;
            int gy = by + ly - 2, gx = bx + lx - 2;
            float v = 0.f;
            if (gy >= 0 && gy < h && gx >= 0 && gx < w)
                v = Ii[(size_t)gy * w + gx];
            sIn[idx] = make_float2(v, v);
        }
    }
    __syncthreads();

    // stage-2 ownership: rows 2r, 2r+1; cols oxq, oxq+1
    const int r   = tid >> 4;            // 0..15
    const int oxq = (tid & 15) * 2;      // 0,2,...,30

    const ull bias2 = pack2(c_pack.b2[pset], 0.f);  // bias once per px (lo)
    ull a00 = bias2, a01 = bias2;        // row 2r,   cols oxq, oxq+1
    ull a10 = bias2, a11 = bias2;        // row 2r+1

#pragma unroll 1
    for (int g = 0; g < 2; g++) {
        if (interior)
            stage1<false>(sIn, sHb, pset, g, by, bx, h, w, tid);
        else
            stage1<true>(sIn, sHb, pset, g, by, bx, h, w, tid);
        __syncthreads();

        const ull* w0A = c_pack.w2[pset][4 * g + 0];
        const ull* w0B = w0A + 9;
        const ull* w1A = c_pack.w2[pset][4 * g + 2];
        const ull* w1B = w1A + 9;

        // --- stage 2 partial: conv 8->1, 2 output rows sharing hidden rows ---
#pragma unroll
        for (int hr = 0; hr < 4; hr++) {
            const int hy = 2 * r + hr;
            unsigned base = (unsigned)(hy * 36 + oxq) * 32;

            ull A0[4], B0[4], A1[4], B1[4];
#pragma unroll
            for (int j = 0; j < 4; j++) {
                unsigned a = swz64(base + j * 32);
                ulonglong2 v0 = *(const ulonglong2*)(sHb + a);
                ulonglong2 v1 = *(const ulonglong2*)(sHb + (a ^ 16));
                A0[j] = v0.x; B0[j] = v0.y;
                A1[j] = v1.x; B1[j] = v1.y;
            }

            if (hr <= 2) {            // contributes to row 2r (dy = hr)
#pragma unroll
                for (int t = 0; t < 3; t++) {
                    ull wa = w0A[hr * 3 + t], wb = w0B[hr * 3 + t];
                    a00 = fma2(wa, A0[t],     a00);
                    a01 = fma2(wa, A0[t + 1], a01);
                    a00 = fma2(wb, B0[t],     a00);
                    a01 = fma2(wb, B0[t + 1], a01);
                    ull wc = w1A[hr * 3 + t], wd = w1B[hr * 3 + t];
                    a00 = fma2(wc, A1[t],     a00);
                    a01 = fma2(wc, A1[t + 1], a01);
                    a00 = fma2(wd, B1[t],     a00);
                    a01 = fma2(wd, B1[t + 1], a01);
                }
            }
            if (hr >= 1) {            // contributes to row 2r+1 (dy = hr-1)
#pragma unroll
                for (int t = 0; t < 3; t++) {
                    ull wa = w0A[(hr - 1) * 3 + t], wb = w0B[(hr - 1) * 3 + t];
                    a10 = fma2(wa, A0[t],     a10);
                    a11 = fma2(wa, A0[t + 1], a11);
                    a10 = fma2(wb, B0[t],     a10);
                    a11 = fma2(wb, B0[t + 1], a11);
                    ull wc = w1A[(hr - 1) * 3 + t], wd = w1B[(hr - 1) * 3 + t];
                    a10 = fma2(wc, A1[t],     a10);
                    a11 = fma2(wc, A1[t + 1], a11);
                    a10 = fma2(wd, B1[t],     a10);
                    a11 = fma2(wd, B1[t + 1], a11);
                }
            }
        }
        if (g == 0) __syncthreads();   // before next pass overwrites sH
    }

    // --- epilogue: O = S + sign*acc, float2 per row ---
    float2 f00 = unpack2(a00), f01 = unpack2(a01);
    float2 f10 = unpack2(a10), f11 = unpack2(a11);

    const float* Si = S + (size_t)img * h * w;
    float* Oi = O + (size_t)img * h * w;
    size_t p0 = (size_t)(by + 2 * r) * w + bx + oxq;
    size_t p1 = p0 + w;

    float2 s0 = *(const float2*)(Si + p0);
    float2 s1 = *(const float2*)(Si + p1);
    float2 o0, o1;
    o0.x = s0.x + sign * (f00.x + f00.y);
    o0.y = s0.y + sign * (f01.x + f01.y);
    o1.x = s1.x + sign * (f10.x + f10.y);
    o1.y = s1.y + sign * (f11.x + f11.y);
    *(float2*)(Oi + p0) = o0;
    *(float2*)(Oi + p1) = o1;
}

// ---------------------------------------------------------------------------
// Kernel 3: transpose + even/odd split (L and H via grid.z).
// ---------------------------------------------------------------------------
__global__ void transpose_split_kernel(const float* __restrict__ Lsrc,
                                       const float* __restrict__ Hsrc,
                                       float* __restrict__ LLd, float* __restrict__ HLd,
                                       float* __restrict__ LHd, float* __restrict__ HHd,
                                       int h, int w)
{
    __shared__ float tile[32][65];
    int z = blockIdx.z;
    int which = z / NIMG, img = z - which * NIMG;
    const float* T = which ? Hsrc : Lsrc;
    float* E = which ? LHd : LLd;
    float* O = which ? HHd : HLd;

    const int c0 = blockIdx.x * 32;
    const int r0 = blockIdx.y * 32;
    const int tx = threadIdx.x, ty = threadIdx.y;

    const float* Ti = T + (size_t)img * h * w;
#pragma unroll
    for (int k = 0; k < 4; k++) {
        int cc = ty + 8 * k;
        const float* row = Ti + (size_t)(c0 + cc) * w + 2 * r0;
        tile[cc][tx]      = row[tx];
        tile[cc][tx + 32] = row[tx + 32];
    }
    __syncthreads();

    size_t imgo = (size_t)img * (w / 2) * h;
#pragma unroll
    for (int k = 0; k < 4; k++) {
        int rr = ty + 8 * k;
        size_t o = imgo + (size_t)(r0 + rr) * h + c0 + tx;
        E[o] = tile[tx][2 * rr];
        O[o] = tile[tx][2 * rr + 1];
    }
}

// ---------------------------------------------------------------------------
// Kernel 4: gather. out[b, q*3+c, i, j] = Q_q[c*8+b, j, i]
// ---------------------------------------------------------------------------
__global__ void gather_kernel(const float* __restrict__ LL, const float* __restrict__ HL,
                              const float* __restrict__ LH, const float* __restrict__ HH,
                              float* __restrict__ out)
{
    __shared__ float tile[32][33];
    int z = blockIdx.z;
    int q = z / NIMG, img = z - q * NIMG;
    const float* Q = (q == 0) ? LL : (q == 1) ? HL : (q == 2) ? LH : HH;
    int b = img & 7, cch = img >> 3;
    int chan = q * 3 + cch;

    int i0 = blockIdx.x * 32, j0 = blockIdx.y * 32;
    int tx = threadIdx.x, ty = threadIdx.y;

    const float* Qi = Q + (size_t)img * 65536;
#pragma unroll
    for (int k = 0; k < 4; k++) {
        int jj = ty + 8 * k;
        tile[jj][tx] = Qi[(size_t)(j0 + jj) * 256 + i0 + tx];
    }
    __syncthreads();

    float* o = out + ((size_t)b * 12 + chan) * 65536;
#pragma unroll
    for (int k = 0; k < 4; k++) {
        int ii = ty + 8 * k;
        o[(size_t)(i0 + ii) * 256 + j0 + tx] = tile[tx][ii];
    }
}

// ---------------------------------------------------------------------------
extern "C" void kernel_launch(void* const* d_in, const int* in_sizes, int n_in,
                              void* d_out, int out_size)
{
    const float* x   = (const float*)d_in[0];
    const float* Wp1 = (const float*)d_in[1];
    const float* bp1 = (const float*)d_in[2];
    const float* Wp2 = (const float*)d_in[3];
    const float* bp2 = (const float*)d_in[4];
    const float* Wu1 = (const float*)d_in[5];
    const float* bu1 = (const float*)d_in[6];
    const float* Wu2 = (const float*)d_in[7];
    const float* bu2 = (const float*)d_in[8];
    float* out = (float*)d_out;

    // opt in to >48KB dynamic SMEM (idempotent)
    cudaFuncSetAttribute(subnet_lift_kernel,
                         cudaFuncAttributeMaxDynamicSharedMemorySize, SMEM_TOTAL);

    // pack weights on device, then stage into __constant__
    prep_kernel<<<1, 256>>>(Wp1, bp1, Wp2, bp2, Wu1, bu1, Wu2, bu2);
    PackedW* pg;
    cudaGetSymbolAddress((void**)&pg, g_pack);
    cudaMemcpyToSymbolAsync(c_pack, pg, sizeof(PackedW), 0, cudaMemcpyDeviceToDevice);

    float *pL, *pH, *pLL, *pHL, *pLH, *pHH;
    cudaGetSymbolAddress((void**)&pL,  g_L);
    cudaGetSymbolAddress((void**)&pH,  g_H);
    cudaGetSymbolAddress((void**)&pLL, g_LL);
    cudaGetSymbolAddress((void**)&pHL, g_HL);
    cudaGetSymbolAddress((void**)&pLH, g_LH);
    cudaGetSymbolAddress((void**)&pHH, g_HH);

    // 1) rgb->yuv + row split
    yuv_split_kernel<<<dim3(1024, 8), 256>>>(x, pL, pH);

    // 2) lift 1 (rows), 24 x 256 x 512 ; tiles 32w x 32h
    dim3 g1(512 / 32, 256 / 32, NIMG);
    subnet_lift_kernel<<<g1, 256, SMEM_TOTAL>>>(pL, pH, pH, pL, pH, pH,
                                                0, -1.f, 256, 512);
    subnet_lift_kernel<<<g1, 256, SMEM_TOTAL>>>(pH, pL, pL, pH, pL, pL,
                                                1, +1.f, 256, 512);

    // 3) transpose + column split
    dim3 gt(256 / 32, 256 / 32, 2 * NIMG);
    transpose_split_kernel<<<gt, dim3(32, 8)>>>(pL, pH, pLL, pHL, pLH, pHH, 256, 512);

    // 4) lift 2 (L branch) and lift 3 (H branch) fused per step, grid.z = 48
    dim3 g2(256 / 32, 256 / 32, 2 * NIMG);
    subnet_lift_kernel<<<g2, 256, SMEM_TOTAL>>>(pLL, pHL, pHL, pLH, pHH, pHH,
                                                0, -1.f, 256, 256);
    subnet_lift_kernel<<<g2, 256, SMEM_TOTAL>>>(pHL, pLL, pLL, pHH, pLH, pLH,
                                                1, +1.f, 256, 256);

    // 5) transpose back + batch2channel + concat -> out [8,12,256,256]
    gather_kernel<<<dim3(8, 8, 96), dim3(32, 8)>>>(pLL, pHL, pLH, pHH, out);
}